// round 4
// baseline (speedup 1.0000x reference)
#include <cuda_runtime.h>
#include <math_constants.h>
#include <cstdint>

// Scratch (no allocations allowed): per-(b,chunk) partial m, l, ctx[32].
__device__ float g_pm[8192];
__device__ float g_pl[8192];
__device__ float g_pctx[8192 * 32];

#define FMA2(acc, a, w) \
    asm("fma.rn.f32x2 %0, %1, %2, %0;" : "+l"(acc) : "l"(a), "l"(w))
#define FMA2O(dst, a, b_, c_) \
    asm("fma.rn.f32x2 %0, %1, %2, %3;" : "=l"(dst) : "l"(a), "l"(b_), "l"(c_))
#define DUP2(dst, s) \
    asm("mov.b64 %0, {%1, %1};" : "=l"(dst) : "f"(s))
#define MUL2(dst, a, b_) \
    asm("mul.rn.f32x2 %0, %1, %2;" : "=l"(dst) : "l"(a), "l"(b_))
#define UNPK2(lo, hi, s) \
    asm("mov.b64 {%0, %1}, %2;" : "=f"(lo), "=f"(hi) : "l"(s))

// ---------------------------------------------------------------------------
// Kernel 1: fused keys-GEMM + tanh-score + online-softmax + context partials.
// Grid (S/512, B), 256 threads. ONE 64-row group per warp (2 rows per lane).
// The 8 KB/warp stage is fetched with cp.async issued at kernel entry, so the
// DRAM latency is hidden behind the Wk/query prologue + __syncthreads.
// ---------------------------------------------------------------------------
__global__ __launch_bounds__(256, 2)
void attn_main(const float* __restrict__ lstm, const float* __restrict__ fh,
               const float* __restrict__ Wq, const float* __restrict__ bq,
               const float* __restrict__ Wk, const float* __restrict__ bk,
               const float* __restrict__ Wv, const float* __restrict__ bv,
               float* __restrict__ out_scores, int S)
{
    const int b     = blockIdx.y;
    const int chunk = blockIdx.x;
    const int nCh   = gridDim.x;
    const int tid   = threadIdx.x;
    const int w     = tid >> 5;
    const int lane  = tid & 31;

    extern __shared__ __align__(16) float dyn[];
    float* sWk = dyn;                       // 1024 floats
    float* sX  = dyn + 1024;                // 8 warps * 2048 floats (64 rows)

    __shared__ __align__(16) float sQC[32]; // q[d] * 2log2e
    __shared__ __align__(16) float sBk[32];
    __shared__ float sNW[32];               // -2 * wv[d]
    __shared__ float sRed[8 * 32], sMw[8], sLw[8], sW1;

    // ---- FIRST: kick off this warp's 64-row stage with cp.async ----
    const int gs = chunk * 512 + w * 64;    // first row of this warp's group
    float* xb = sX + w * 2048;              // 64 rows x 32 floats (swizzled f4)
    if (gs < S) {
        const char* gsrc =
            (const char*)(lstm + ((size_t)b * S + gs) * 32);
        const int maxIdx = (S - gs) * 8 - 1;          // last valid 16B chunk
        #pragma unroll
        for (int k = 0; k < 16; ++k) {
            const int idx = k * 32 + lane;            // 0..511
            const int row = idx >> 3, c = idx & 7;
            const int dstV = row * 8 + (c ^ (row & 7));
            unsigned long long saddr =
                __cvta_generic_to_shared(xb + dstV * 4);
            const char* src = gsrc + (size_t)min(idx, maxIdx) * 16;
            asm volatile("cp.async.cg.shared.global [%0], [%1], 16;"
                         :: "l"(saddr), "l"(src));
        }
    }
    asm volatile("cp.async.commit_group;");

    // ---- prologue (overlaps the cp.async DRAM latency) ----
    ((float4*)sWk)[tid] = ((const float4*)Wk)[tid];
    if (tid < 32) {
        sBk[tid] = bk[tid];
        const float wv = Wv[tid];
        sNW[tid] = -2.f * wv;
        float acc = bq[tid];
        #pragma unroll
        for (int h = 0; h < 32; ++h)
            acc = fmaf(fh[b * 32 + h], Wq[h * 32 + tid], acc);
        sQC[tid] = acc * 2.8853900817779268f;   // 2*log2(e)
        float t = wv;                            // sW1 = bv + sum_d wv[d]
        #pragma unroll
        for (int off = 16; off; off >>= 1)
            t += __shfl_xor_sync(0xffffffffu, t, off);
        if (tid == 0) sW1 = bv[0] + t;
    }
    __syncthreads();

    const float w1 = sW1;
    float m = -CUDART_INF_F, l = 0.f;
    unsigned long long ctx2[16];
    #pragma unroll
    for (int j = 0; j < 16; ++j) ctx2[j] = 0ull;

    const float4* xbuf = (const float4*)xb;
    const ulonglong2* sWkq = (const ulonglong2*)sWk;
    const ulonglong2* sBk2 = (const ulonglong2*)sBk;
    const unsigned long long* qc2 = (const unsigned long long*)sQC;

    unsigned long long Cdup;                 // 2*log2(e)
    DUP2(Cdup, 2.8853900817779268f);

    if (gs < S) {
        asm volatile("cp.async.wait_group 0;");
        __syncwarp();

        // ---- keys GEMM: two rows per lane (lane, lane+32) ----
        unsigned long long acc[2][16];
        #pragma unroll
        for (int j = 0; j < 8; ++j) {
            ulonglong2 t = sBk2[j];
            acc[0][2 * j] = t.x; acc[0][2 * j + 1] = t.y;
            acc[1][2 * j] = t.x; acc[1][2 * j + 1] = t.y;
        }
        #pragma unroll
        for (int jx = 0; jx < 8; ++jx) {
            const int sw = jx ^ (lane & 7);
            float4 xqA = xbuf[lane * 8 + sw];
            float4 xqB = xbuf[(lane + 32) * 8 + sw];
            float xsA[4] = {xqA.x, xqA.y, xqA.z, xqA.w};
            float xsB[4] = {xqB.x, xqB.y, xqB.z, xqB.w};
            #pragma unroll
            for (int i = 0; i < 4; ++i) {
                unsigned long long aA, aB;
                DUP2(aA, xsA[i]);
                DUP2(aB, xsB[i]);
                const int h = jx * 4 + i;
                #pragma unroll
                for (int j2 = 0; j2 < 8; ++j2) {
                    ulonglong2 w2 = sWkq[h * 8 + j2];   // broadcast LDS.128
                    FMA2(acc[0][2 * j2],     aA, w2.x);
                    FMA2(acc[0][2 * j2 + 1], aA, w2.y);
                    FMA2(acc[1][2 * j2],     aB, w2.x);
                    FMA2(acc[1][2 * j2 + 1], aB, w2.y);
                }
            }
        }

        // ---- per-row: score + online-softmax + ctx update ----
        #pragma unroll
        for (int r = 0; r < 2; ++r) {
            const int srow = gs + r * 32 + lane;
            if (srow >= S) continue;

            float s0 = 0.f, s1 = 0.f, s2 = 0.f, s3 = 0.f;
            #pragma unroll
            for (int j = 0; j < 16; ++j) {
                unsigned long long a2;
                FMA2O(a2, acc[r][j], Cdup, qc2[j]);
                float a0, a1;
                UNPK2(a0, a1, a2);
                float e0, e1;
                asm("ex2.approx.f32 %0, %1;" : "=f"(e0) : "f"(a0));
                asm("ex2.approx.f32 %0, %1;" : "=f"(e1) : "f"(a1));
                float r0, r1;
                asm("rcp.approx.f32 %0, %1;" : "=f"(r0) : "f"(e0 + 1.f));
                asm("rcp.approx.f32 %0, %1;" : "=f"(r1) : "f"(e1 + 1.f));
                if (j & 1) { s2 = fmaf(r0, sNW[2 * j], s2); s3 = fmaf(r1, sNW[2 * j + 1], s3); }
                else       { s0 = fmaf(r0, sNW[2 * j], s0); s1 = fmaf(r1, sNW[2 * j + 1], s1); }
            }
            const float score = w1 + ((s0 + s1) + (s2 + s3));

            out_scores[(size_t)b * S + srow] = score;   // raw, coalesced

            const float m_new = fmaxf(m, score);
            const float c = __expf(m - m_new);          // 0 on first pass
            const float p = __expf(score - m_new);
            l = fmaf(l, c, p);
            unsigned long long c2, p2;
            DUP2(c2, c); DUP2(p2, p);
            #pragma unroll
            for (int j = 0; j < 16; ++j) {
                unsigned long long t;
                MUL2(t, acc[r][j], p2);
                asm("fma.rn.f32x2 %0, %0, %1, %2;" : "+l"(ctx2[j]) : "l"(c2), "l"(t));
            }
            m = m_new;
        }
    } else {
        asm volatile("cp.async.wait_group 0;");
    }

    // ---- CTA reduction of (m, l, ctx[32]) ----
    float ctx[32];
    #pragma unroll
    for (int j = 0; j < 16; ++j) UNPK2(ctx[2 * j], ctx[2 * j + 1], ctx2[j]);

    float wm = m;
    #pragma unroll
    for (int off = 16; off; off >>= 1)
        wm = fmaxf(wm, __shfl_xor_sync(0xffffffffu, wm, off));
    if (lane == 0) sMw[w] = wm;
    __syncthreads();
    float Mcta = sMw[0];
    #pragma unroll
    for (int ww = 1; ww < 8; ++ww) Mcta = fmaxf(Mcta, sMw[ww]);

    const float scale = (m > -CUDART_INF_F) ? __expf(m - Mcta) : 0.f;
    float lp = l * scale;
    #pragma unroll
    for (int d = 0; d < 32; ++d) ctx[d] *= scale;

    #pragma unroll
    for (int off = 16; off; off >>= 1) {
        lp += __shfl_xor_sync(0xffffffffu, lp, off);
        #pragma unroll
        for (int d = 0; d < 32; ++d)
            ctx[d] += __shfl_xor_sync(0xffffffffu, ctx[d], off);
    }
    if (lane == 0) {
        sLw[w] = lp;
        #pragma unroll
        for (int d = 0; d < 32; ++d) sRed[w * 32 + d] = ctx[d];
    }
    __syncthreads();

    if (tid < 32) {
        float cs = 0.f;
        #pragma unroll
        for (int ww = 0; ww < 8; ++ww) cs += sRed[ww * 32 + tid];
        const int pc = b * nCh + chunk;
        g_pctx[pc * 32 + tid] = cs;
        if (tid == 0) {
            float ls = 0.f;
            #pragma unroll
            for (int ww = 0; ww < 8; ++ww) ls += sLw[ww];
            g_pm[pc] = Mcta;
            g_pl[pc] = ls;
        }
    }
}

// ---------------------------------------------------------------------------
// Kernel 2 (fused): per-b merge of chunk partials -> context output, then
// normalize raw scores into softmax weights. One block per b.
// ---------------------------------------------------------------------------
__global__ __launch_bounds__(256)
void attn_finish(float* __restrict__ out_ctx, float* __restrict__ wout,
                 int S, int nCh)
{
    const int b = blockIdx.x;
    const int tid = threadIdx.x;

    __shared__ float sM, sInv;

    if (tid < 32) {
        float M = -CUDART_INF_F;
        for (int c = 0; c < nCh; ++c) M = fmaxf(M, g_pm[b * nCh + c]);
        float L = 0.f, cs = 0.f;
        for (int c = 0; c < nCh; ++c) {
            const float sc = __expf(g_pm[b * nCh + c] - M);
            L  += g_pl[b * nCh + c] * sc;
            cs += g_pctx[(b * nCh + c) * 32 + tid] * sc;
        }
        const float invL = 1.f / L;
        out_ctx[b * 32 + tid] = cs * invL;
        if (tid == 0) { sM = M; sInv = invL; }
    }
    __syncthreads();

    const float M = sM, inv = sInv;
    float* wrow = wout + (size_t)b * S;
    for (int i = tid; i < S; i += 256)
        wrow[i] = __expf(wrow[i] - M) * inv;
}

// ---------------------------------------------------------------------------
extern "C" void kernel_launch(void* const* d_in, const int* in_sizes, int n_in,
                              void* d_out, int out_size)
{
    const float* lstm = (const float*)d_in[0];
    const float* fh   = (const float*)d_in[1];
    const float* Wq   = (const float*)d_in[2];
    const float* bq   = (const float*)d_in[3];
    const float* Wk   = (const float*)d_in[4];
    const float* bk   = (const float*)d_in[5];
    const float* Wv   = (const float*)d_in[6];
    const float* bv   = (const float*)d_in[7];

    const int BH = in_sizes[1];           // B * H
    const int B  = BH / 32;
    const int S  = in_sizes[0] / BH;
    const int nCh = (S + 511) / 512;

    float* out_ctx = (float*)d_out;                 // [B, 32]
    float* scores  = out_ctx + (size_t)B * 32;      // [B, S]

    const int smemBytes = (1024 + 8 * 2048) * (int)sizeof(float);  // 68 KB
    static bool attrSet = false;
    if (!attrSet) {
        cudaFuncSetAttribute(attn_main,
                             cudaFuncAttributeMaxDynamicSharedMemorySize,
                             smemBytes);
        attrSet = true;
    }

    dim3 grid(nCh, B);
    attn_main<<<grid, 256, smemBytes>>>(lstm, fh, Wq, bq, Wk, bk, Wv, bv,
                                        scores, S);
    attn_finish<<<B, 256>>>(out_ctx, scores, S, nCh);
}

// round 5
// speedup vs baseline: 1.0798x; 1.0798x over previous
#include <cuda_runtime.h>
#include <math_constants.h>
#include <cstdint>

// Scratch (no allocations allowed).
__device__ float g_qc[8192];          // (bq + fh*Wq)*2log2e, [B,32]
__device__ float g_nw[32];            // -2*Wv
__device__ float g_w1[1];             // bv + sum(Wv)
__device__ float g_pm[32768];         // per-warp-group partial max
__device__ float g_pl[32768];         // per-warp-group partial sum
__device__ float g_pctx[32768 * 32];  // per-warp-group partial context
__device__ float g_M[2048];
__device__ float g_invL[2048];

#define FMA2(acc, a, w) \
    asm("fma.rn.f32x2 %0, %1, %2, %0;" : "+l"(acc) : "l"(a), "l"(w))
#define FMA2O(dst, a, b_, c_) \
    asm("fma.rn.f32x2 %0, %1, %2, %3;" : "=l"(dst) : "l"(a), "l"(b_), "l"(c_))
#define DUP2(dst, s) \
    asm("mov.b64 %0, {%1, %1};" : "=l"(dst) : "f"(s))
#define MUL2(dst, a, b_) \
    asm("mul.rn.f32x2 %0, %1, %2;" : "=l"(dst) : "l"(a), "l"(b_))
#define UNPK2(lo, hi, s) \
    asm("mov.b64 {%0, %1}, %2;" : "=f"(lo), "=f"(hi) : "l"(s))

// ---------------------------------------------------------------------------
// Kernel 0: per-batch query precompute (off the main kernel's critical path).
// ---------------------------------------------------------------------------
__global__ __launch_bounds__(256)
void attn_pre(const float* __restrict__ fh, const float* __restrict__ Wq,
              const float* __restrict__ bq, const float* __restrict__ Wv,
              const float* __restrict__ bv, int B)
{
    const int idx = blockIdx.x * 256 + threadIdx.x;
    const int b = idx >> 5, d = idx & 31;
    if (b < B) {
        float acc = bq[d];
        #pragma unroll
        for (int h = 0; h < 32; ++h)
            acc = fmaf(fh[b * 32 + h], Wq[h * 32 + d], acc);
        g_qc[idx] = acc * 2.8853900817779268f;   // * 2*log2(e)
    }
    if (blockIdx.x == 0 && threadIdx.x < 32)
        g_nw[threadIdx.x] = -2.f * Wv[threadIdx.x];
    if (blockIdx.x == 0 && threadIdx.x == 0) {
        float s = bv[0];
        #pragma unroll
        for (int d2 = 0; d2 < 32; ++d2) s += Wv[d2];
        g_w1[0] = s;
    }
}

// ---------------------------------------------------------------------------
// Kernel 1: fused keys-GEMM + tanh-score + softmax partials + context partials.
// Grid (S/256, B), 128 threads (4 warps), 5 CTAs/SM. Warp owns 64 rows
// (2 per lane), staged by cp.async issued at kernel entry. Warp-autonomous
// epilogue: per-warp (m, l, ctx[32]) partial straight to global scratch.
// ---------------------------------------------------------------------------
__global__ __launch_bounds__(128, 5)
void attn_main(const float* __restrict__ lstm, const float* __restrict__ Wk,
               const float* __restrict__ bk, float* __restrict__ out_scores,
               int S)
{
    const int b     = blockIdx.y;
    const int chunk = blockIdx.x;
    const int tid   = threadIdx.x;
    const int w     = tid >> 5;
    const int lane  = tid & 31;

    extern __shared__ __align__(16) float dyn[];
    float* sWk = dyn;                       // 1024 floats
    float* sX  = dyn + 1024;                // 4 warps * 2048 floats

    __shared__ __align__(16) float sQC[32];
    __shared__ __align__(16) float sBk[32];
    __shared__ float sNW[32];
    __shared__ float sW1;

    // ---- FIRST: this warp's 64-row stage via cp.async ----
    const int gs = chunk * 256 + w * 64;
    float* xb = sX + w * 2048;
    if (gs < S) {
        const char* gsrc = (const char*)(lstm + ((size_t)b * S + gs) * 32);
        const int maxIdx = (S - gs) * 8 - 1;
        #pragma unroll
        for (int k = 0; k < 16; ++k) {
            const int idx = k * 32 + lane;           // 0..511 16B chunks
            const int row = idx >> 3, c = idx & 7;
            const int dstV = row * 8 + (c ^ (row & 7));
            unsigned long long saddr = __cvta_generic_to_shared(xb + dstV * 4);
            const char* src = gsrc + (size_t)min(idx, maxIdx) * 16;
            asm volatile("cp.async.cg.shared.global [%0], [%1], 16;"
                         :: "l"(saddr), "l"(src));
        }
    }
    asm volatile("cp.async.commit_group;");

    // ---- prologue (overlaps cp.async DRAM latency) ----
    ((float4*)sWk)[tid]       = ((const float4*)Wk)[tid];
    ((float4*)sWk)[tid + 128] = ((const float4*)Wk)[tid + 128];
    if (tid < 32) {
        sQC[tid] = g_qc[b * 32 + tid];
        sNW[tid] = g_nw[tid];
        sBk[tid] = bk[tid];
    }
    if (tid == 0) sW1 = g_w1[0];
    __syncthreads();

    const float w1 = sW1;
    const ulonglong2* sWkq = (const ulonglong2*)sWk;
    const ulonglong2* sBk2 = (const ulonglong2*)sBk;
    const unsigned long long* qc2 = (const unsigned long long*)sQC;

    unsigned long long Cdup;                 // 2*log2(e)
    DUP2(Cdup, 2.8853900817779268f);

    const int nP = gridDim.x * 4;            // warp-groups per batch
    const int pg = (b * gridDim.x + chunk) * 4 + w;

    if (gs >= S) {                           // dead warp-group (tail)
        asm volatile("cp.async.wait_group 0;");
        if (lane == 0) { g_pm[pg] = -CUDART_INF_F; g_pl[pg] = 0.f; }
        g_pctx[pg * 32 + lane] = 0.f;
        return;
    }

    asm volatile("cp.async.wait_group 0;");
    __syncwarp();

    // ---- keys GEMM: rows (gs+lane, gs+32+lane) ----
    const float4* xbuf = (const float4*)xb;
    unsigned long long acc[2][16];
    #pragma unroll
    for (int j = 0; j < 8; ++j) {
        ulonglong2 t = sBk2[j];
        acc[0][2 * j] = t.x; acc[0][2 * j + 1] = t.y;
        acc[1][2 * j] = t.x; acc[1][2 * j + 1] = t.y;
    }
    #pragma unroll
    for (int jx = 0; jx < 8; ++jx) {
        const int sw = jx ^ (lane & 7);
        float4 xqA = xbuf[lane * 8 + sw];
        float4 xqB = xbuf[(lane + 32) * 8 + sw];
        float xsA[4] = {xqA.x, xqA.y, xqA.z, xqA.w};
        float xsB[4] = {xqB.x, xqB.y, xqB.z, xqB.w};
        #pragma unroll
        for (int i = 0; i < 4; ++i) {
            unsigned long long aA, aB;
            DUP2(aA, xsA[i]);
            DUP2(aB, xsB[i]);
            const int h = jx * 4 + i;
            #pragma unroll
            for (int j2 = 0; j2 < 8; ++j2) {
                ulonglong2 w2 = sWkq[h * 8 + j2];    // broadcast LDS.128
                FMA2(acc[0][2 * j2],     aA, w2.x);
                FMA2(acc[0][2 * j2 + 1], aA, w2.y);
                FMA2(acc[1][2 * j2],     aB, w2.x);
                FMA2(acc[1][2 * j2 + 1], aB, w2.y);
            }
        }
    }

    // ---- scores for both rows ----
    const bool valid0 = (gs + lane) < S;
    const bool valid1 = (gs + 32 + lane) < S;
    float sc[2];
    #pragma unroll
    for (int r = 0; r < 2; ++r) {
        float s0 = 0.f, s1 = 0.f, s2 = 0.f, s3 = 0.f;
        #pragma unroll
        for (int j = 0; j < 16; ++j) {
            unsigned long long a2;
            FMA2O(a2, acc[r][j], Cdup, qc2[j]);
            float a0, a1;
            UNPK2(a0, a1, a2);
            float e0, e1;
            asm("ex2.approx.f32 %0, %1;" : "=f"(e0) : "f"(a0));
            asm("ex2.approx.f32 %0, %1;" : "=f"(e1) : "f"(a1));
            float r0, r1;
            asm("rcp.approx.f32 %0, %1;" : "=f"(r0) : "f"(e0 + 1.f));
            asm("rcp.approx.f32 %0, %1;" : "=f"(r1) : "f"(e1 + 1.f));
            if (j & 1) { s2 = fmaf(r0, sNW[2 * j], s2); s3 = fmaf(r1, sNW[2 * j + 1], s3); }
            else       { s0 = fmaf(r0, sNW[2 * j], s0); s1 = fmaf(r1, sNW[2 * j + 1], s1); }
        }
        sc[r] = w1 + ((s0 + s1) + (s2 + s3));
    }
    if (!valid0) sc[0] = -CUDART_INF_F;
    if (!valid1) sc[1] = -CUDART_INF_F;

    if (valid0) out_scores[(size_t)b * S + gs + lane]      = sc[0];
    if (valid1) out_scores[(size_t)b * S + gs + 32 + lane] = sc[1];

    // ---- warp max, exp, combine ctx in place ----
    float mr = fmaxf(sc[0], sc[1]);
    #pragma unroll
    for (int off = 16; off; off >>= 1)
        mr = fmaxf(mr, __shfl_xor_sync(0xffffffffu, mr, off));

    const float p0 = valid0 ? __expf(sc[0] - mr) : 0.f;
    const float p1 = valid1 ? __expf(sc[1] - mr) : 0.f;
    float lsum = p0 + p1;
    #pragma unroll
    for (int off = 16; off; off >>= 1)
        lsum += __shfl_xor_sync(0xffffffffu, lsum, off);

    unsigned long long p0d, p1d;
    DUP2(p0d, p0); DUP2(p1d, p1);
    #pragma unroll
    for (int j = 0; j < 16; ++j) {
        MUL2(acc[0][j], acc[0][j], p0d);     // acc0 = key0*p0
        FMA2(acc[0][j], acc[1][j], p1d);     // acc0 += key1*p1
    }

    // ---- warp transpose-reduce of ctx[32] in the dead stage buffer ----
    float* sR = xb;                          // 32 x 33 floats, conflict-free
    __syncwarp();
    #pragma unroll
    for (int j = 0; j < 16; ++j) {
        float lo, hi;
        UNPK2(lo, hi, acc[0][j]);
        sR[lane * 33 + 2 * j]     = lo;
        sR[lane * 33 + 2 * j + 1] = hi;
    }
    __syncwarp();
    float cs = 0.f;
    #pragma unroll
    for (int l2 = 0; l2 < 32; ++l2)
        cs += sR[l2 * 33 + lane];

    g_pctx[pg * 32 + lane] = cs;
    if (lane == 0) { g_pm[pg] = mr; g_pl[pg] = lsum; }
    (void)nP;
}

// ---------------------------------------------------------------------------
// Kernel 2: merge per-warp-group partials per batch -> context + (M, 1/L).
// ---------------------------------------------------------------------------
__global__ __launch_bounds__(32)
void attn_fin(float* __restrict__ out_ctx, int nP)
{
    const int b = blockIdx.x;
    const int d = threadIdx.x;

    float M = -CUDART_INF_F;
    #pragma unroll 4
    for (int c = 0; c < nP; ++c) M = fmaxf(M, g_pm[b * nP + c]);

    float L = 0.f, cs = 0.f;
    #pragma unroll 4
    for (int c = 0; c < nP; ++c) {
        const float sc = __expf(g_pm[b * nP + c] - M);
        L  = fmaf(g_pl[b * nP + c], sc, L);
        cs = fmaf(g_pctx[(b * nP + c) * 32 + d], sc, cs);
    }
    const float invL = 1.f / L;
    out_ctx[b * 32 + d] = cs * invL;
    if (d == 0) { g_M[b] = M; g_invL[b] = invL; }
}

// ---------------------------------------------------------------------------
// Kernel 3: normalize raw scores in-place into softmax weights (float4).
// ---------------------------------------------------------------------------
__global__ __launch_bounds__(256)
void attn_norm(float* __restrict__ wout, int S)
{
    const int b  = blockIdx.y;
    const int i4 = blockIdx.x * 256 + threadIdx.x;
    const float M = g_M[b], inv = g_invL[b];
    float* base = wout + (size_t)b * S;
    if (i4 * 4 + 3 < S) {
        float4* p = (float4*)base + i4;
        float4 v = *p;
        v.x = __expf(v.x - M) * inv;
        v.y = __expf(v.y - M) * inv;
        v.z = __expf(v.z - M) * inv;
        v.w = __expf(v.w - M) * inv;
        *p = v;
    } else {
        for (int i = i4 * 4; i < S; ++i)
            base[i] = __expf(base[i] - M) * inv;
    }
}

// ---------------------------------------------------------------------------
extern "C" void kernel_launch(void* const* d_in, const int* in_sizes, int n_in,
                              void* d_out, int out_size)
{
    const float* lstm = (const float*)d_in[0];
    const float* fh   = (const float*)d_in[1];
    const float* Wq   = (const float*)d_in[2];
    const float* bq   = (const float*)d_in[3];
    const float* Wk   = (const float*)d_in[4];
    const float* bk   = (const float*)d_in[5];
    const float* Wv   = (const float*)d_in[6];
    const float* bv   = (const float*)d_in[7];

    const int BH = in_sizes[1];            // B * H
    const int B  = BH / 32;
    const int S  = in_sizes[0] / BH;
    const int nCh = (S + 255) / 256;

    float* out_ctx = (float*)d_out;                 // [B, 32]
    float* scores  = out_ctx + (size_t)B * 32;      // [B, S]

    attn_pre<<<(B * 32 + 255) / 256, 256>>>(fh, Wq, bq, Wv, bv, B);

    const int smemBytes = (1024 + 4 * 2048) * (int)sizeof(float);  // 36 KB
    dim3 grid(nCh, B);
    attn_main<<<grid, 128, smemBytes>>>(lstm, Wk, bk, scores, S);

    attn_fin<<<B, 32>>>(out_ctx, nCh * 4);

    dim3 ngrid((S / 4 + 255) / 256, B);
    attn_norm<<<ngrid, 256>>>(scores, S);
}